// round 2
// baseline (speedup 1.0000x reference)
#include <cuda_runtime.h>
#include <cuda_bf16.h>

// Problem constants
#define B_   64
#define NE_  40000
#define NR_  500
#define D1_  200
#define D2_  200
#define L_   64
#define KSPLIT 40          // k2 chunk = D2_/KSPLIT = 5
#define LOG2E 1.4426950408889634f

// ---------------- scratch (device globals; no allocation) ----------------
__device__ __align__(16) float g_x0T[D1_ * B_];          // [i][b]
__device__ __align__(16) float g_rT [D2_ * B_];          // [k][b]
__device__ __align__(16) float g_a  [B_ * L_];           // [b][l] : (n_h - c)*k_l
__device__ __align__(16) float g_w  [B_ * L_];           // [b][l] : nf[r_idx]
__device__ __align__(16) float g_ypart[KSPLIT * B_ * D1_];
__device__ __align__(16) float g_y  [B_ * D1_];          // [b][j]
__device__ __align__(16) float g_x1T[D1_ * B_];          // [d][b]

__device__ __forceinline__ float ex2f(float x) {
    float r; asm("ex2.approx.ftz.f32 %0, %1;" : "=f"(r) : "f"(x)); return r;
}
__device__ __forceinline__ float rcpf(float x) {
    float r; asm("rcp.approx.ftz.f32 %0, %1;" : "=f"(r) : "f"(x)); return r;
}

// ---------------- kernel 1: gather + BN0 + branch prep ----------------
__global__ void k_prep(const int* __restrict__ e1_idx, const int* __restrict__ r_idx,
                       const float* __restrict__ E, const float* __restrict__ R,
                       const float* __restrict__ lits, const float* __restrict__ c,
                       const float* __restrict__ var_l, const float* __restrict__ nf,
                       const float* __restrict__ g0, const float* __restrict__ b0) {
    __shared__ int se1[B_], sr[B_];
    int t = threadIdx.x;
    if (t < B_) { se1[t] = e1_idx[t]; sr[t] = r_idx[t]; }
    __syncthreads();

    // BN0 per column j (training-mode, biased var over batch of 64)
    for (int j = t; j < D1_; j += blockDim.x) {
        float sum = 0.f, sq = 0.f;
        float vals[B_];
#pragma unroll
        for (int b = 0; b < B_; b++) {
            float v = E[(long)se1[b] * D1_ + j];
            vals[b] = v; sum += v; sq += v * v;
        }
        float mu  = sum * (1.f / B_);
        float var = sq * (1.f / B_) - mu * mu;
        float sc  = g0[j] * rsqrtf(var + 1e-5f);
        float be  = b0[j];
#pragma unroll
        for (int b = 0; b < B_; b++)
            g_x0T[j * B_ + b] = (vals[b] - mu) * sc + be;
    }
    // gather R transposed [k][b]
    for (int idx = t; idx < D2_ * B_; idx += blockDim.x) {
        int k = idx >> 6, b = idx & 63;
        g_rT[idx] = R[(long)sr[b] * D2_ + k];
    }
    // branch prep: a[b][l], w[b][l]
    for (int idx = t; idx < B_ * L_; idx += blockDim.x) {
        int b = idx >> 6, l = idx & 63;
        float ks = sqrtf(LOG2E / var_l[l]);
        g_a[idx] = (lits[(long)se1[b] * L_ + l] - c[l]) * ks;
        g_w[idx] = nf[(long)sr[b] * L_ + l];
    }
}

// ---------------- kernel 2: W contraction GEMM (deterministic k-split) ----------------
// y[b,j] = sum_{k2,i} rT[k2][b] * x0T[i][b] * W[k2,i,j]
// grid: (7 j-tiles of 32, KSPLIT), block 256 = 64 b x 4 jgroups, 8 j per thread
__global__ void k_wgemm(const float* __restrict__ W) {
    int jt = blockIdx.x;          // 0..6
    int ks = blockIdx.y;          // 0..KSPLIT-1
    int t  = threadIdx.x;
    int b  = t & 63;
    int jg = t >> 6;              // 0..3
    int j0 = jt * 32;

    __shared__ __align__(16) float Ws[20][32];

    float acc[8];
#pragma unroll
    for (int u = 0; u < 8; u++) acc[u] = 0.f;

#pragma unroll 1
    for (int kc = 0; kc < D2_ / KSPLIT; kc++) {
        int k2 = ks * (D2_ / KSPLIT) + kc;
        float rv = g_rT[k2 * B_ + b];
#pragma unroll 1
        for (int i0 = 0; i0 < D1_; i0 += 20) {
            __syncthreads();
            // stage W[k2][i0..i0+19][j0..j0+31], zero-pad j >= 200
            for (int idx = t; idx < 20 * 32; idx += 256) {
                int il = idx >> 5, jl = idx & 31;
                int j = j0 + jl;
                Ws[il][jl] = (j < D1_)
                    ? W[((long)k2 * D1_ + (i0 + il)) * D1_ + j] : 0.f;
            }
            __syncthreads();
#pragma unroll
            for (int il = 0; il < 20; il++) {
                float xv = g_x0T[(i0 + il) * B_ + b];
                float z  = rv * xv;
                const float4* wp = (const float4*)&Ws[il][jg * 8];
                float4 w0 = wp[0], w1 = wp[1];
                acc[0] += z * w0.x; acc[1] += z * w0.y;
                acc[2] += z * w0.z; acc[3] += z * w0.w;
                acc[4] += z * w1.x; acc[5] += z * w1.y;
                acc[6] += z * w1.z; acc[7] += z * w1.w;
            }
        }
    }
    float* yp = &g_ypart[ks * (B_ * D1_)];
    int j = j0 + jg * 8;
#pragma unroll
    for (int u = 0; u < 8; u++)
        if (j + u < D1_) yp[b * D1_ + j + u] = acc[u];
}

// ---------------- kernel 3: reduce k-split partials ----------------
__global__ void k_reduce() {
    int idx = blockIdx.x * 256 + threadIdx.x;
    if (idx >= B_ * D1_) return;
    float s = 0.f;
#pragma unroll
    for (int ks = 0; ks < KSPLIT; ks++) s += g_ypart[ks * (B_ * D1_) + idx];
    g_y[idx] = s;
}

// ---------------- kernel 4: BN1 -> x1T[d][b] ----------------
__global__ void k_bn1(const float* __restrict__ g1, const float* __restrict__ b1) {
    int t = threadIdx.x;
    for (int d = t; d < D1_; d += blockDim.x) {
        float sum = 0.f, sq = 0.f;
        float vals[B_];
#pragma unroll
        for (int b = 0; b < B_; b++) {
            float v = g_y[b * D1_ + d];
            vals[b] = v; sum += v; sq += v * v;
        }
        float mu  = sum * (1.f / B_);
        float var = sq * (1.f / B_) - mu * mu;
        float sc  = g1[d] * rsqrtf(var + 1e-5f);
        float be  = b1[d];
#pragma unroll
        for (int b = 0; b < B_; b++)
            g_x1T[d * B_ + b] = (vals[b] - mu) * sc + be;
    }
}

// ---------------- kernel 5: fused score_l + KBLN + sigmoid ----------------
// grid: 625 blocks (64 n each), block 512 = 64 b x 8 ngroups, 8 n per thread
__global__ __launch_bounds__(512) void k_score(
    const float* __restrict__ E, const float* __restrict__ lits,
    const float* __restrict__ var_l, float* __restrict__ out) {

    __shared__ __align__(16) float Es[32][68];   // transposed E tile [d][n], padded
    __shared__ __align__(16) float Ss[64][64];   // scaled lits tile [n][l]
    __shared__ float ksc[L_];

    int t  = threadIdx.x;
    int b  = t & 63;
    int ng = t >> 6;                 // 0..7
    int n0 = blockIdx.x * 64;

    if (t < L_) ksc[t] = sqrtf(LOG2E / var_l[t]);
    __syncthreads();

    // stage scaled lits tile: Ss[nl][l] = lits[n0+nl][l] * k_l
    {
        int l = t & 63, nr = t >> 6;
        for (int nl = nr; nl < 64; nl += 8)
            Ss[nl][l] = lits[(long)(n0 + nl) * L_ + l] * ksc[l];
    }

    float acc[8];
#pragma unroll
    for (int u = 0; u < 8; u++) acc[u] = 0.f;

    // -------- score_l: dot over d of x1T[d][b] * E[n][d] --------
#pragma unroll 1
    for (int d0 = 0; d0 < D1_; d0 += 32) {
        int dc = min(32, D1_ - d0);
        __syncthreads();
        {
            int dl = t & 31, nr = t >> 5;   // 16 n-rows per pass
            if (dl < dc)
                for (int nl = nr; nl < 64; nl += 16)
                    Es[dl][nl] = E[(long)(n0 + nl) * D1_ + d0 + dl];
        }
        __syncthreads();
#pragma unroll 4
        for (int dl = 0; dl < dc; dl++) {
            float xv = g_x1T[(d0 + dl) * B_ + b];
            const float4* ep = (const float4*)&Es[dl][ng * 8];
            float4 e0 = ep[0], e1 = ep[1];
            acc[0] += xv * e0.x; acc[1] += xv * e0.y;
            acc[2] += xv * e0.z; acc[3] += xv * e0.w;
            acc[4] += xv * e1.x; acc[5] += xv * e1.y;
            acc[6] += xv * e1.z; acc[7] += xv * e1.w;
        }
    }

    // -------- KBLN: acc[nn] += sum_l w[b,l] * exp2(-(a[b,l]-s[n,l])^2) --------
    const float4* ap = (const float4*)&g_a[b * L_];
    const float4* wp = (const float4*)&g_w[b * L_];
#pragma unroll 1
    for (int lc = 0; lc < 8; lc++) {
        float4 a0 = ap[lc * 2], a1 = ap[lc * 2 + 1];
        float4 w0 = wp[lc * 2], w1 = wp[lc * 2 + 1];
        float av[8] = {a0.x, a0.y, a0.z, a0.w, a1.x, a1.y, a1.z, a1.w};
        float wv[8] = {w0.x, w0.y, w0.z, w0.w, w1.x, w1.y, w1.z, w1.w};
#pragma unroll
        for (int nn = 0; nn < 8; nn++) {
            const float4* sp = (const float4*)&Ss[ng * 8 + nn][lc * 8];
            float4 s0 = sp[0], s1 = sp[1];
            float sv[8] = {s0.x, s0.y, s0.z, s0.w, s1.x, s1.y, s1.z, s1.w};
            float part = 0.f;
#pragma unroll
            for (int u = 0; u < 8; u++) {
                float dq = av[u] - sv[u];
                float ph = ex2f(-dq * dq);
                part += wv[u] * ph;
            }
            acc[nn] += part;
        }
    }

    // -------- sigmoid + store --------
#pragma unroll
    for (int nn = 0; nn < 8; nn++) {
        float e = ex2f(-LOG2E * acc[nn]);
        acc[nn] = rcpf(1.f + e);
    }
    int n = n0 + ng * 8;
    float4* op = (float4*)&out[(long)b * NE_ + n];
    op[0] = make_float4(acc[0], acc[1], acc[2], acc[3]);
    op[1] = make_float4(acc[4], acc[5], acc[6], acc[7]);
}

// ---------------- launch ----------------
extern "C" void kernel_launch(void* const* d_in, const int* in_sizes, int n_in,
                              void* d_out, int out_size) {
    const int*   e1_idx = (const int*)  d_in[0];
    const int*   r_idx  = (const int*)  d_in[1];
    const float* E      = (const float*)d_in[2];
    const float* R      = (const float*)d_in[3];
    const float* W      = (const float*)d_in[4];
    const float* lits   = (const float*)d_in[5];
    const float* c      = (const float*)d_in[6];
    const float* var_l  = (const float*)d_in[7];
    const float* nf     = (const float*)d_in[8];
    const float* g0     = (const float*)d_in[9];
    const float* b0     = (const float*)d_in[10];
    const float* g1     = (const float*)d_in[11];
    const float* b1     = (const float*)d_in[12];
    float* out = (float*)d_out;

    k_prep<<<1, 256>>>(e1_idx, r_idx, E, R, lits, c, var_l, nf, g0, b0);
    k_wgemm<<<dim3(7, KSPLIT), 256>>>(W);
    k_reduce<<<(B_ * D1_ + 255) / 256, 256>>>();
    k_bn1<<<1, 256>>>(g1, b1);
    k_score<<<NE_ / 64, 512>>>(E, lits, var_l, out);
}

// round 4
// speedup vs baseline: 1.3933x; 1.3933x over previous
#include <cuda_runtime.h>
#include <cuda_bf16.h>

// Problem constants
#define B_   64
#define NE_  40000
#define NR_  500
#define D1_  200
#define D2_  200
#define L_   64
#define KSPLIT 40          // k2 chunk = 5
#define LOG2E 1.4426950408889634f

// ---------------- scratch (device globals; no allocation) ----------------
__device__ __align__(16) float g_x0T[D1_ * B_];          // [i][b]
__device__ __align__(16) float g_rT [D2_ * B_];          // [k][b]
__device__ __align__(16) float g_aT [L_ * B_];           // [l][b] : (n_h - c)*k_l
__device__ __align__(16) float g_wT [L_ * B_];           // [l][b] : nf[r_idx]
__device__ __align__(16) float g_ypart[KSPLIT * D1_ * B_]; // [ks][j][b]
__device__ __align__(16) float g_x1T[D1_ * B_];          // [d][b]

__device__ __forceinline__ float ex2f(float x) {
    float r; asm("ex2.approx.ftz.f32 %0, %1;" : "=f"(r) : "f"(x)); return r;
}
__device__ __forceinline__ float rcpf(float x) {
    float r; asm("rcp.approx.ftz.f32 %0, %1;" : "=f"(r) : "f"(x)); return r;
}

// ---------------- kernel 1: gather + BN0 + branch prep ----------------
__global__ void k_prep(const int* __restrict__ e1_idx, const int* __restrict__ r_idx,
                       const float* __restrict__ E, const float* __restrict__ R,
                       const float* __restrict__ lits, const float* __restrict__ c,
                       const float* __restrict__ var_l, const float* __restrict__ nf,
                       const float* __restrict__ g0, const float* __restrict__ b0) {
    __shared__ int se1[B_], sr[B_];
    int t = threadIdx.x;
    if (t < B_) { se1[t] = e1_idx[t]; sr[t] = r_idx[t]; }
    __syncthreads();

    // BN0 per column j (training-mode, biased var over batch of 64)
    for (int j = t; j < D1_; j += blockDim.x) {
        float sum = 0.f, sq = 0.f;
        float vals[B_];
#pragma unroll
        for (int b = 0; b < B_; b++) {
            float v = E[(long)se1[b] * D1_ + j];
            vals[b] = v; sum += v; sq += v * v;
        }
        float mu  = sum * (1.f / B_);
        float var = sq * (1.f / B_) - mu * mu;
        float sc  = g0[j] * rsqrtf(var + 1e-5f);
        float be  = b0[j];
#pragma unroll
        for (int b = 0; b < B_; b++)
            g_x0T[j * B_ + b] = (vals[b] - mu) * sc + be;
    }
    // gather R transposed [k][b]
    for (int idx = t; idx < D2_ * B_; idx += blockDim.x) {
        int k = idx >> 6, b = idx & 63;
        g_rT[idx] = R[(long)sr[b] * D2_ + k];
    }
    // branch prep (transposed [l][b]): a, w
    for (int idx = t; idx < B_ * L_; idx += blockDim.x) {
        int b = idx & 63, l = idx >> 6;
        float ks = sqrtf(LOG2E / var_l[l]);
        g_aT[l * B_ + b] = (lits[(long)se1[b] * L_ + l] - c[l]) * ks;
        g_wT[l * B_ + b] = nf[(long)sr[b] * L_ + l];
    }
}

// ---------------- kernel 2: W contraction GEMM (deterministic k-split) ----------------
// y[b,j] = sum_{k2,i} rT[k2][b] * x0T[i][b] * W[k2,i,j]
// grid (7 j-tiles of 32, KSPLIT), block 256 = 64 b x 4 jg (8 j each)
__global__ __launch_bounds__(256) void k_wgemm(const float* __restrict__ W) {
    int jt = blockIdx.x;          // 0..6
    int ks = blockIdx.y;          // 0..39
    int t  = threadIdx.x;
    int b  = t & 63;
    int jg = t >> 6;              // 0..3
    int j0 = jt * 32;

    __shared__ __align__(16) float Ws[5][20][32];

    float rv[5];
#pragma unroll
    for (int kc = 0; kc < 5; kc++) rv[kc] = g_rT[(ks * 5 + kc) * B_ + b];

    float acc[8];
#pragma unroll
    for (int u = 0; u < 8; u++) acc[u] = 0.f;

#pragma unroll 1
    for (int i0 = 0; i0 < D1_; i0 += 20) {
        __syncthreads();
        // stage W[ks*5..+4][i0..i0+19][j0..j0+31]
        for (int idx = t; idx < 5 * 20 * 32; idx += 256) {
            int jl = idx & 31;
            int il = (idx >> 5) % 20;
            int kc = idx / (32 * 20);
            int j  = j0 + jl;
            Ws[kc][il][jl] = (j < D1_)
                ? W[((long)(ks * 5 + kc) * D1_ + (i0 + il)) * D1_ + j] : 0.f;
        }
        __syncthreads();
#pragma unroll 2
        for (int il = 0; il < 20; il++) {
            float xv = g_x0T[(i0 + il) * B_ + b];
#pragma unroll
            for (int kc = 0; kc < 5; kc++) {
                float z = rv[kc] * xv;
                const float4* wp = (const float4*)&Ws[kc][il][jg * 8];
                float4 w0 = wp[0], w1 = wp[1];
                acc[0] += z * w0.x; acc[1] += z * w0.y;
                acc[2] += z * w0.z; acc[3] += z * w0.w;
                acc[4] += z * w1.x; acc[5] += z * w1.y;
                acc[6] += z * w1.z; acc[7] += z * w1.w;
            }
        }
    }
    // store partials in [ks][j][b] layout
    float* yp = &g_ypart[ks * (D1_ * B_)];
    int j = j0 + jg * 8;
#pragma unroll
    for (int u = 0; u < 8; u++)
        if (j + u < D1_) yp[(j + u) * B_ + b] = acc[u];
}

// ---------------- kernel 3: fused k-split reduce + BN1 -> x1T[d][b] ----------------
// grid 25 x 256: warp per j (200 warps); lane covers b = lane, lane+32
__global__ void k_bn1r(const float* __restrict__ g1, const float* __restrict__ b1) {
    int j    = blockIdx.x * 8 + (threadIdx.x >> 5);
    int lane = threadIdx.x & 31;
    float y0 = 0.f, y1 = 0.f;
#pragma unroll 8
    for (int ks = 0; ks < KSPLIT; ks++) {
        y0 += g_ypart[ks * (D1_ * B_) + j * B_ + lane];
        y1 += g_ypart[ks * (D1_ * B_) + j * B_ + 32 + lane];
    }
    float s = y0 + y1, q = y0 * y0 + y1 * y1;
#pragma unroll
    for (int off = 16; off >= 1; off >>= 1) {
        s += __shfl_xor_sync(0xffffffffu, s, off);
        q += __shfl_xor_sync(0xffffffffu, q, off);
    }
    float mu  = s * (1.f / B_);
    float var = q * (1.f / B_) - mu * mu;
    float sc  = g1[j] * rsqrtf(var + 1e-5f);
    float be  = b1[j];
    g_x1T[j * B_ + lane]      = (y0 - mu) * sc + be;
    g_x1T[j * B_ + 32 + lane] = (y1 - mu) * sc + be;
}

// ---------------- kernel 4: fused score_l + KBLN + sigmoid ----------------
// grid 625 (64 n each), block 256 = 8 warps(ng, 8 n each) x 32 lanes (b = 2*lane, 2*lane+1)
__global__ __launch_bounds__(256) void k_score(
    const float* __restrict__ E, const float* __restrict__ lits,
    const float* __restrict__ var_l, float* __restrict__ out) {

    __shared__ __align__(16) float Es[40][68];   // E tile transposed [d][n], pad 68
    __shared__ __align__(16) float Ss[64][64];   // scaled lits [n][l]
    __shared__ float ksc[L_];

    int t    = threadIdx.x;
    int lane = t & 31;
    int warp = t >> 5;               // n-group 0..7
    int n0   = blockIdx.x * 64;

    if (t < L_) ksc[t] = sqrtf(LOG2E / var_l[t]);
    __syncthreads();

    // stage scaled lits tile (consumed after later syncs)
    for (int i = t; i < 64 * 64; i += 256) {
        int l = i & 63, nl = i >> 6;
        Ss[nl][l] = lits[(long)(n0 + nl) * L_ + l] * ksc[l];
    }

    float acc0[8], acc1[8];
#pragma unroll
    for (int u = 0; u < 8; u++) { acc0[u] = 0.f; acc1[u] = 0.f; }

    // -------- score_l: 5 chunks of 40 d --------
    const float2* x2 = (const float2*)g_x1T;
#pragma unroll 1
    for (int ch = 0; ch < 5; ch++) {
        int d0 = ch * 40;
        __syncthreads();
        for (int i = t; i < 40 * 64; i += 256) {
            int dl = i % 40, nl = i / 40;
            Es[dl][nl] = E[(long)(n0 + nl) * D1_ + d0 + dl];
        }
        __syncthreads();
#pragma unroll 8
        for (int dl = 0; dl < 40; dl++) {
            float2 xv = x2[(d0 + dl) * 32 + lane];
            const float4* ep = (const float4*)&Es[dl][warp * 8];
            float4 e0 = ep[0], e1 = ep[1];
            acc0[0] += xv.x * e0.x; acc1[0] += xv.y * e0.x;
            acc0[1] += xv.x * e0.y; acc1[1] += xv.y * e0.y;
            acc0[2] += xv.x * e0.z; acc1[2] += xv.y * e0.z;
            acc0[3] += xv.x * e0.w; acc1[3] += xv.y * e0.w;
            acc0[4] += xv.x * e1.x; acc1[4] += xv.y * e1.x;
            acc0[5] += xv.x * e1.y; acc1[5] += xv.y * e1.y;
            acc0[6] += xv.x * e1.z; acc1[6] += xv.y * e1.z;
            acc0[7] += xv.x * e1.w; acc1[7] += xv.y * e1.w;
        }
    }

    // -------- KBLN: acc[nn] += sum_l w[b,l] * exp2(-(a[b,l]-s[n,l])^2) --------
    const float2* aT2 = (const float2*)g_aT;
    const float2* wT2 = (const float2*)g_wT;
#pragma unroll 1
    for (int lc = 0; lc < 8; lc++) {
        float2 a2[8], w2[8];
#pragma unroll
        for (int u = 0; u < 8; u++) {
            a2[u] = aT2[(lc * 8 + u) * 32 + lane];
            w2[u] = wT2[(lc * 8 + u) * 32 + lane];
        }
#pragma unroll
        for (int nn = 0; nn < 8; nn++) {
            const float4* sp = (const float4*)&Ss[warp * 8 + nn][lc * 8];
            float4 s0 = sp[0], s1 = sp[1];
            float sv[8] = {s0.x, s0.y, s0.z, s0.w, s1.x, s1.y, s1.z, s1.w};
            float p0 = 0.f, p1 = 0.f;
#pragma unroll
            for (int u = 0; u < 8; u++) {
                float d0v = a2[u].x - sv[u];
                float d1v = a2[u].y - sv[u];
                p0 += w2[u].x * ex2f(-d0v * d0v);
                p1 += w2[u].y * ex2f(-d1v * d1v);
            }
            acc0[nn] += p0; acc1[nn] += p1;
        }
    }

    // -------- sigmoid + store (2 rows x 8 n per thread) --------
    int b0 = 2 * lane;
    int n  = n0 + warp * 8;
#pragma unroll
    for (int u = 0; u < 8; u++) {
        acc0[u] = rcpf(1.f + ex2f(-LOG2E * acc0[u]));
        acc1[u] = rcpf(1.f + ex2f(-LOG2E * acc1[u]));
    }
    float4* o0 = (float4*)&out[(long)b0 * NE_ + n];
    o0[0] = make_float4(acc0[0], acc0[1], acc0[2], acc0[3]);
    o0[1] = make_float4(acc0[4], acc0[5], acc0[6], acc0[7]);
    float4* o1 = (float4*)&out[(long)(b0 + 1) * NE_ + n];
    o1[0] = make_float4(acc1[0], acc1[1], acc1[2], acc1[3]);
    o1[1] = make_float4(acc1[4], acc1[5], acc1[6], acc1[7]);
}

// ---------------- launch ----------------
extern "C" void kernel_launch(void* const* d_in, const int* in_sizes, int n_in,
                              void* d_out, int out_size) {
    const int*   e1_idx = (const int*)  d_in[0];
    const int*   r_idx  = (const int*)  d_in[1];
    const float* E      = (const float*)d_in[2];
    const float* R      = (const float*)d_in[3];
    const float* W      = (const float*)d_in[4];
    const float* lits   = (const float*)d_in[5];
    const float* c      = (const float*)d_in[6];
    const float* var_l  = (const float*)d_in[7];
    const float* nf     = (const float*)d_in[8];
    const float* g0     = (const float*)d_in[9];
    const float* b0     = (const float*)d_in[10];
    const float* g1     = (const float*)d_in[11];
    const float* b1     = (const float*)d_in[12];
    float* out = (float*)d_out;

    k_prep<<<1, 256>>>(e1_idx, r_idx, E, R, lits, c, var_l, nf, g0, b0);
    k_wgemm<<<dim3(7, KSPLIT), 256>>>(W);
    k_bn1r<<<25, 256>>>(g1, b1);
    k_score<<<NE_ / 64, 256>>>(E, lits, var_l, out);
}

// round 6
// speedup vs baseline: 1.4140x; 1.0148x over previous
#include <cuda_runtime.h>
#include <cuda_bf16.h>

// Problem constants
#define B_   64
#define NE_  40000
#define NR_  500
#define D1_  200
#define D2_  200
#define L_   64
#define KSPLIT 50          // k2 chunk = 4
#define LOG2E 1.4426950408889634f

// ---------------- scratch (device globals; no allocation) ----------------
__device__ __align__(16) float g_x0T[D1_ * B_];          // [i][b]
__device__ __align__(16) float g_rT [D2_ * B_];          // [k][b]
__device__ __align__(16) float g_aT [L_ * B_];           // [l][b] : (n_h - c)*k_l
__device__ __align__(16) float g_wT [L_ * B_];           // [l][b] : nf[r_idx]
__device__ __align__(16) float g_ypart[KSPLIT * D1_ * B_]; // [ks][j][b]
__device__ __align__(16) float g_x1T[D1_ * B_];          // [d][b]

__device__ __forceinline__ float ex2f(float x) {
    float r; asm("ex2.approx.ftz.f32 %0, %1;" : "=f"(r) : "f"(x)); return r;
}
__device__ __forceinline__ float rcpf(float x) {
    float r; asm("rcp.approx.ftz.f32 %0, %1;" : "=f"(r) : "f"(x)); return r;
}

// ---------------- kernel 1: parallel gather + BN0 + branch prep ----------------
// blocks 0..24: BN0 (warp per j, 8 warps/block)
// blocks 25,26: gather rT ; block 27: aT/wT prep
__global__ void k_prep(const int* __restrict__ e1_idx, const int* __restrict__ r_idx,
                       const float* __restrict__ E, const float* __restrict__ R,
                       const float* __restrict__ lits, const float* __restrict__ c,
                       const float* __restrict__ var_l, const float* __restrict__ nf,
                       const float* __restrict__ g0, const float* __restrict__ b0) {
    int blk = blockIdx.x;
    int t = threadIdx.x;
    if (blk < 25) {
        __shared__ int se1[B_];
        if (t < B_) se1[t] = e1_idx[t];
        __syncthreads();
        int j    = blk * 8 + (t >> 5);
        int lane = t & 31;
        float v0 = E[(long)se1[lane] * D1_ + j];
        float v1 = E[(long)se1[lane + 32] * D1_ + j];
        float s = v0 + v1, q = v0 * v0 + v1 * v1;
#pragma unroll
        for (int off = 16; off >= 1; off >>= 1) {
            s += __shfl_xor_sync(0xffffffffu, s, off);
            q += __shfl_xor_sync(0xffffffffu, q, off);
        }
        float mu  = s * (1.f / B_);
        float var = q * (1.f / B_) - mu * mu;
        float sc  = g0[j] * rsqrtf(var + 1e-5f);
        float be  = b0[j];
        g_x0T[j * B_ + lane]      = (v0 - mu) * sc + be;
        g_x0T[j * B_ + 32 + lane] = (v1 - mu) * sc + be;
    } else if (blk < 27) {
        __shared__ int sr[B_];
        if (t < B_) sr[t] = r_idx[t];
        __syncthreads();
        int base = (blk - 25) * (D2_ * B_ / 2);
        for (int idx = t; idx < D2_ * B_ / 2; idx += 256) {
            int k = (base + idx) >> 6, b = (base + idx) & 63;
            g_rT[base + idx] = R[(long)sr[b] * D2_ + k];
        }
    } else {
        __shared__ int se1[B_], sr[B_];
        if (t < B_) { se1[t] = e1_idx[t]; sr[t] = r_idx[t]; }
        __syncthreads();
        for (int idx = t; idx < B_ * L_; idx += 256) {
            int b = idx & 63, l = idx >> 6;
            float ks = sqrtf(LOG2E / var_l[l]);
            g_aT[l * B_ + b] = (lits[(long)se1[b] * L_ + l] - c[l]) * ks;
            g_wT[l * B_ + b] = nf[(long)sr[b] * L_ + l];
        }
    }
}

// ---------------- kernel 2: W contraction GEMM (double-buffered, k-split) ----------------
// y[b,j] = sum_{k2,i} rT[k2][b] * x0T[i][b] * W[k2,i,j]
// grid (7 j-tiles of 32, KSPLIT=50), block 256 = 64 b x 4 jg (8 j each)
__global__ __launch_bounds__(256) void k_wgemm(const float* __restrict__ W) {
    int jt = blockIdx.x;          // 0..6
    int ks = blockIdx.y;          // 0..49
    int t  = threadIdx.x;
    int b  = t & 63;
    int jg = t >> 6;              // 0..3
    int j0 = jt * 32;

    __shared__ __align__(16) float Ws[2][4][20][32];

    float rv[4];
#pragma unroll
    for (int kc = 0; kc < 4; kc++) rv[kc] = g_rT[(ks * 4 + kc) * B_ + b];

    float acc[8];
#pragma unroll
    for (int u = 0; u < 8; u++) acc[u] = 0.f;

    // stage chunk ch (i0 = ch*20) into buffer p
    #define STAGE(ch, p) {                                                  \
        int i0_ = (ch) * 20;                                                \
        for (int idx = t; idx < 4 * 20 * 32; idx += 256) {                  \
            int jl = idx & 31;                                              \
            int il = (idx >> 5) % 20;                                       \
            int kc = idx / 640;                                             \
            int j  = j0 + jl;                                               \
            Ws[p][kc][il][jl] = (j < D1_)                                   \
                ? W[((long)(ks * 4 + kc) * D1_ + (i0_ + il)) * D1_ + j] : 0.f; \
        }                                                                   \
    }

    STAGE(0, 0);
#pragma unroll 1
    for (int ch = 0; ch < 10; ch++) {
        __syncthreads();
        if (ch < 9) STAGE(ch + 1, (ch + 1) & 1);
        int p  = ch & 1;
        int i0 = ch * 20;
#pragma unroll 4
        for (int il = 0; il < 20; il++) {
            float xv = g_x0T[(i0 + il) * B_ + b];
#pragma unroll
            for (int kc = 0; kc < 4; kc++) {
                float z = rv[kc] * xv;
                const float4* wp = (const float4*)&Ws[p][kc][il][jg * 8];
                float4 w0 = wp[0], w1 = wp[1];
                acc[0] += z * w0.x; acc[1] += z * w0.y;
                acc[2] += z * w0.z; acc[3] += z * w0.w;
                acc[4] += z * w1.x; acc[5] += z * w1.y;
                acc[6] += z * w1.z; acc[7] += z * w1.w;
            }
        }
    }
    #undef STAGE

    float* yp = &g_ypart[ks * (D1_ * B_)];
    int j = j0 + jg * 8;
#pragma unroll
    for (int u = 0; u < 8; u++)
        if (j + u < D1_) yp[(j + u) * B_ + b] = acc[u];
}

// ---------------- kernel 3: fused k-split reduce + BN1 -> x1T[d][b] ----------------
__global__ void k_bn1r(const float* __restrict__ g1, const float* __restrict__ b1) {
    int j    = blockIdx.x * 8 + (threadIdx.x >> 5);
    int lane = threadIdx.x & 31;
    float y0 = 0.f, y1 = 0.f;
#pragma unroll 10
    for (int ks = 0; ks < KSPLIT; ks++) {
        y0 += g_ypart[ks * (D1_ * B_) + j * B_ + lane];
        y1 += g_ypart[ks * (D1_ * B_) + j * B_ + 32 + lane];
    }
    float s = y0 + y1, q = y0 * y0 + y1 * y1;
#pragma unroll
    for (int off = 16; off >= 1; off >>= 1) {
        s += __shfl_xor_sync(0xffffffffu, s, off);
        q += __shfl_xor_sync(0xffffffffu, q, off);
    }
    float mu  = s * (1.f / B_);
    float var = q * (1.f / B_) - mu * mu;
    float sc  = g1[j] * rsqrtf(var + 1e-5f);
    float be  = b1[j];
    g_x1T[j * B_ + lane]      = (y0 - mu) * sc + be;
    g_x1T[j * B_ + 32 + lane] = (y1 - mu) * sc + be;
}

// ---------------- kernel 4: fused score_l + KBLN (interleaved) + sigmoid ----------------
// grid 625 (64 n each), block 256 = 8 warps(ng, 8 n each) x 32 lanes (b = 2*lane, 2*lane+1)
// KBLN work (16 sub-chunks of 4 literals) is distributed across the 5 E-chunk
// iterations so MUFU (EX2) and FMA (dot) pipes overlap across warps.
__global__ __launch_bounds__(256, 4) void k_score(
    const float* __restrict__ E, const float* __restrict__ lits,
    const float* __restrict__ var_l, float* __restrict__ out) {

    __shared__ __align__(16) float Es[40][68];   // E tile transposed [d][n], pad 68
    __shared__ __align__(16) float Ss[64][64];   // scaled lits [n][l]
    __shared__ float ksc[L_];

    int t    = threadIdx.x;
    int lane = t & 31;
    int warp = t >> 5;               // n-group 0..7
    int n0   = blockIdx.x * 64;

    if (t < L_) ksc[t] = sqrtf(LOG2E / var_l[t]);
    __syncthreads();

    // stage scaled lits tile (visible after the first chunk sync)
    for (int i = t; i < 64 * 64; i += 256) {
        int l = i & 63, nl = i >> 6;
        Ss[nl][l] = lits[(long)(n0 + nl) * L_ + l] * ksc[l];
    }

    float acc0[8], acc1[8];
#pragma unroll
    for (int u = 0; u < 8; u++) { acc0[u] = 0.f; acc1[u] = 0.f; }

    const float2* x2  = (const float2*)g_x1T;
    const float2* aT2 = (const float2*)g_aT;
    const float2* wT2 = (const float2*)g_wT;

    int lc_done = 0;
#pragma unroll 1
    for (int ch = 0; ch < 5; ch++) {
        int d0 = ch * 40;
        __syncthreads();
        for (int i = t; i < 40 * 64; i += 256) {
            int dl = i % 40, nl = i / 40;
            Es[dl][nl] = E[(long)(n0 + nl) * D1_ + d0 + dl];
        }
        __syncthreads();
        // -------- score_l partial: 40 d --------
#pragma unroll 8
        for (int dl = 0; dl < 40; dl++) {
            float2 xv = x2[(d0 + dl) * 32 + lane];
            const float4* ep = (const float4*)&Es[dl][warp * 8];
            float4 e0 = ep[0], e1 = ep[1];
            acc0[0] += xv.x * e0.x; acc1[0] += xv.y * e0.x;
            acc0[1] += xv.x * e0.y; acc1[1] += xv.y * e0.y;
            acc0[2] += xv.x * e0.z; acc1[2] += xv.y * e0.z;
            acc0[3] += xv.x * e0.w; acc1[3] += xv.y * e0.w;
            acc0[4] += xv.x * e1.x; acc1[4] += xv.y * e1.x;
            acc0[5] += xv.x * e1.y; acc1[5] += xv.y * e1.y;
            acc0[6] += xv.x * e1.z; acc1[6] += xv.y * e1.z;
            acc0[7] += xv.x * e1.w; acc1[7] += xv.y * e1.w;
        }
        // -------- KBLN partial: 3-4 sub-chunks of 4 literals --------
        int nchunks = (ch == 0) ? 4 : 3;
#pragma unroll 1
        for (int r = 0; r < nchunks; r++) {
            int l0 = lc_done * 4;
            float2 a2[4], w2[4];
#pragma unroll
            for (int u = 0; u < 4; u++) {
                a2[u] = aT2[(l0 + u) * 32 + lane];
                w2[u] = wT2[(l0 + u) * 32 + lane];
            }
#pragma unroll
            for (int nn = 0; nn < 8; nn++) {
                const float4 sv4 = *(const float4*)&Ss[warp * 8 + nn][l0];
                float sv[4] = {sv4.x, sv4.y, sv4.z, sv4.w};
                float p0 = 0.f, p1 = 0.f;
#pragma unroll
                for (int u = 0; u < 4; u++) {
                    float d0v = a2[u].x - sv[u];
                    float d1v = a2[u].y - sv[u];
                    p0 += w2[u].x * ex2f(-d0v * d0v);
                    p1 += w2[u].y * ex2f(-d1v * d1v);
                }
                acc0[nn] += p0; acc1[nn] += p1;
            }
            lc_done++;
        }
    }

    // -------- sigmoid + store (2 rows x 8 n per thread) --------
    int b0 = 2 * lane;
    int n  = n0 + warp * 8;
#pragma unroll
    for (int u = 0; u < 8; u++) {
        acc0[u] = rcpf(1.f + ex2f(-LOG2E * acc0[u]));
        acc1[u] = rcpf(1.f + ex2f(-LOG2E * acc1[u]));
    }
    float4* o0 = (float4*)&out[(long)b0 * NE_ + n];
    o0[0] = make_float4(acc0[0], acc0[1], acc0[2], acc0[3]);
    o0[1] = make_float4(acc0[4], acc0[5], acc0[6], acc0[7]);
    float4* o1 = (float4*)&out[(long)(b0 + 1) * NE_ + n];
    o1[0] = make_float4(acc1[0], acc1[1], acc1[2], acc1[3]);
    o1[1] = make_float4(acc1[4], acc1[5], acc1[6], acc1[7]);
}

// ---------------- launch ----------------
extern "C" void kernel_launch(void* const* d_in, const int* in_sizes, int n_in,
                              void* d_out, int out_size) {
    const int*   e1_idx = (const int*)  d_in[0];
    const int*   r_idx  = (const int*)  d_in[1];
    const float* E      = (const float*)d_in[2];
    const float* R      = (const float*)d_in[3];
    const float* W      = (const float*)d_in[4];
    const float* lits   = (const float*)d_in[5];
    const float* c      = (const float*)d_in[6];
    const float* var_l  = (const float*)d_in[7];
    const float* nf     = (const float*)d_in[8];
    const float* g0     = (const float*)d_in[9];
    const float* b0     = (const float*)d_in[10];
    const float* g1     = (const float*)d_in[11];
    const float* b1     = (const float*)d_in[12];
    float* out = (float*)d_out;

    k_prep<<<28, 256>>>(e1_idx, r_idx, E, R, lits, c, var_l, nf, g0, b0);
    k_wgemm<<<dim3(7, KSPLIT), 256>>>(W);
    k_bn1r<<<25, 256>>>(g1, b1);
    k_score<<<NE_ / 64, 256>>>(E, lits, var_l, out);
}

// round 8
// speedup vs baseline: 1.4903x; 1.0540x over previous
#include <cuda_runtime.h>
#include <cuda_bf16.h>

// Problem constants
#define B_   64
#define NE_  40000
#define NR_  500
#define D1_  200
#define D2_  200
#define L_   64
#define KSPLIT 50          // k2 chunk = 4
#define LOG2E 1.4426950408889634f

typedef unsigned long long u64t;

// ---------------- scratch (device globals; no allocation) ----------------
__device__ __align__(16) float g_x0T[D1_ * B_];          // [i][b]
__device__ __align__(16) float g_rT [D2_ * B_];          // [k][b]
__device__ __align__(16) float g_aT [L_ * B_];           // [l][b] : (n_h - c)*k_l
__device__ __align__(16) float g_wT [L_ * B_];           // [l][b] : nf[r_idx]
__device__ __align__(16) float g_ypart[KSPLIT * D1_ * B_]; // [ks][j][b]
__device__ __align__(16) float g_x1T[D1_ * B_];          // [d][b]

__device__ __forceinline__ float ex2f(float x) {
    float r; asm("ex2.approx.ftz.f32 %0, %1;" : "=f"(r) : "f"(x)); return r;
}
__device__ __forceinline__ float rcpf(float x) {
    float r; asm("rcp.approx.ftz.f32 %0, %1;" : "=f"(r) : "f"(x)); return r;
}
// ---- packed f32x2 helpers (sm_103a) ----
__device__ __forceinline__ u64t pk2(float lo, float hi) {
    u64t r; asm("mov.b64 %0, {%1, %2};" : "=l"(r) : "f"(lo), "f"(hi)); return r;
}
__device__ __forceinline__ float2 up2(u64t p) {
    float2 v; asm("mov.b64 {%0, %1}, %2;" : "=f"(v.x), "=f"(v.y) : "l"(p)); return v;
}
__device__ __forceinline__ u64t add2_(u64t a, u64t b) {
    u64t r; asm("add.rn.f32x2 %0, %1, %2;" : "=l"(r) : "l"(a), "l"(b)); return r;
}
__device__ __forceinline__ u64t mul2_(u64t a, u64t b) {
    u64t r; asm("mul.rn.f32x2 %0, %1, %2;" : "=l"(r) : "l"(a), "l"(b)); return r;
}
__device__ __forceinline__ u64t fma2_(u64t a, u64t b, u64t c) {
    u64t r; asm("fma.rn.f32x2 %0, %1, %2, %3;" : "=l"(r) : "l"(a), "l"(b), "l"(c)); return r;
}

// ---------------- kernel 1: parallel gather + BN0 + branch prep ----------------
__global__ void k_prep(const int* __restrict__ e1_idx, const int* __restrict__ r_idx,
                       const float* __restrict__ E, const float* __restrict__ R,
                       const float* __restrict__ lits, const float* __restrict__ c,
                       const float* __restrict__ var_l, const float* __restrict__ nf,
                       const float* __restrict__ g0, const float* __restrict__ b0) {
    int blk = blockIdx.x;
    int t = threadIdx.x;
    if (blk < 25) {
        __shared__ int se1[B_];
        if (t < B_) se1[t] = e1_idx[t];
        __syncthreads();
        int j    = blk * 8 + (t >> 5);
        int lane = t & 31;
        float v0 = E[(long)se1[lane] * D1_ + j];
        float v1 = E[(long)se1[lane + 32] * D1_ + j];
        float s = v0 + v1, q = v0 * v0 + v1 * v1;
#pragma unroll
        for (int off = 16; off >= 1; off >>= 1) {
            s += __shfl_xor_sync(0xffffffffu, s, off);
            q += __shfl_xor_sync(0xffffffffu, q, off);
        }
        float mu  = s * (1.f / B_);
        float var = q * (1.f / B_) - mu * mu;
        float sc  = g0[j] * rsqrtf(var + 1e-5f);
        float be  = b0[j];
        g_x0T[j * B_ + lane]      = (v0 - mu) * sc + be;
        g_x0T[j * B_ + 32 + lane] = (v1 - mu) * sc + be;
    } else if (blk < 27) {
        __shared__ int sr[B_];
        if (t < B_) sr[t] = r_idx[t];
        __syncthreads();
        int base = (blk - 25) * (D2_ * B_ / 2);
        for (int idx = t; idx < D2_ * B_ / 2; idx += 256) {
            int k = (base + idx) >> 6, b = (base + idx) & 63;
            g_rT[base + idx] = R[(long)sr[b] * D2_ + k];
        }
    } else {
        __shared__ int se1[B_], sr[B_];
        if (t < B_) { se1[t] = e1_idx[t]; sr[t] = r_idx[t]; }
        __syncthreads();
        for (int idx = t; idx < B_ * L_; idx += 256) {
            int b = idx & 63, l = idx >> 6;
            float ks = sqrtf(LOG2E / var_l[l]);
            g_aT[l * B_ + b] = (lits[(long)se1[b] * L_ + l] - c[l]) * ks;
            g_wT[l * B_ + b] = nf[(long)sr[b] * L_ + l];
        }
    }
}

// ---------------- kernel 2: W GEMM (double-buffered, f32x2 pairs over j) ----------------
__global__ __launch_bounds__(256) void k_wgemm(const float* __restrict__ W) {
    int jt = blockIdx.x;          // 0..6
    int ks = blockIdx.y;          // 0..49
    int t  = threadIdx.x;
    int b  = t & 63;
    int jg = t >> 6;              // 0..3
    int j0 = jt * 32;

    __shared__ __align__(16) float Ws[2][4][20][32];

    u64t rv2[4];
#pragma unroll
    for (int kc = 0; kc < 4; kc++) {
        float rv = g_rT[(ks * 4 + kc) * B_ + b];
        rv2[kc] = pk2(rv, rv);
    }

    u64t accp[4];
#pragma unroll
    for (int u = 0; u < 4; u++) accp[u] = pk2(0.f, 0.f);

    #define STAGE(ch, p) {                                                  \
        int i0_ = (ch) * 20;                                                \
        for (int idx = t; idx < 4 * 20 * 32; idx += 256) {                  \
            int jl = idx & 31;                                              \
            int il = (idx >> 5) % 20;                                       \
            int kc = idx / 640;                                             \
            int j  = j0 + jl;                                               \
            Ws[p][kc][il][jl] = (j < D1_)                                   \
                ? W[((long)(ks * 4 + kc) * D1_ + (i0_ + il)) * D1_ + j] : 0.f; \
        }                                                                   \
    }

    STAGE(0, 0);
#pragma unroll 1
    for (int ch = 0; ch < 10; ch++) {
        __syncthreads();
        if (ch < 9) STAGE(ch + 1, (ch + 1) & 1);
        int p  = ch & 1;
        int i0 = ch * 20;
#pragma unroll 4
        for (int il = 0; il < 20; il++) {
            float xv = g_x0T[(i0 + il) * B_ + b];
            u64t xp = pk2(xv, xv);
#pragma unroll
            for (int kc = 0; kc < 4; kc++) {
                u64t z = mul2_(rv2[kc], xp);
                const ulonglong2* wp = (const ulonglong2*)&Ws[p][kc][il][jg * 8];
                ulonglong2 wa = wp[0], wb = wp[1];
                accp[0] = fma2_(z, wa.x, accp[0]);
                accp[1] = fma2_(z, wa.y, accp[1]);
                accp[2] = fma2_(z, wb.x, accp[2]);
                accp[3] = fma2_(z, wb.y, accp[3]);
            }
        }
    }
    #undef STAGE

    float* yp = &g_ypart[ks * (D1_ * B_)];
    int j = j0 + jg * 8;
#pragma unroll
    for (int u = 0; u < 4; u++) {
        float2 v = up2(accp[u]);
        if (j + 2 * u     < D1_) yp[(j + 2 * u)     * B_ + b] = v.x;
        if (j + 2 * u + 1 < D1_) yp[(j + 2 * u + 1) * B_ + b] = v.y;
    }
}

// ---------------- kernel 3: fused k-split reduce + BN1 -> x1T[d][b] ----------------
__global__ void k_bn1r(const float* __restrict__ g1, const float* __restrict__ b1) {
    int j    = blockIdx.x * 8 + (threadIdx.x >> 5);
    int lane = threadIdx.x & 31;
    float y0 = 0.f, y1 = 0.f;
#pragma unroll 10
    for (int ks = 0; ks < KSPLIT; ks++) {
        y0 += g_ypart[ks * (D1_ * B_) + j * B_ + lane];
        y1 += g_ypart[ks * (D1_ * B_) + j * B_ + 32 + lane];
    }
    float s = y0 + y1, q = y0 * y0 + y1 * y1;
#pragma unroll
    for (int off = 16; off >= 1; off >>= 1) {
        s += __shfl_xor_sync(0xffffffffu, s, off);
        q += __shfl_xor_sync(0xffffffffu, q, off);
    }
    float mu  = s * (1.f / B_);
    float var = q * (1.f / B_) - mu * mu;
    float sc  = g1[j] * rsqrtf(var + 1e-5f);
    float be  = b1[j];
    g_x1T[j * B_ + lane]      = (y0 - mu) * sc + be;
    g_x1T[j * B_ + 32 + lane] = (y1 - mu) * sc + be;
}

// ---------------- kernel 4: fused score (f32x2 pairs over n) ----------------
// grid 625 (64 n), block 256 = 8 warps (8 n each) x 32 lanes (b = 2*lane, 2*lane+1)
// Accumulators are n-pairs: acc0p[np] = (b0, n even|odd), acc1p[np] = (b1, ...).
__global__ __launch_bounds__(256) void k_score(
    const float* __restrict__ E, const float* __restrict__ lits,
    const float* __restrict__ var_l, float* __restrict__ out) {

    __shared__ __align__(16) float Es[40][68];    // E tile [d][n], pad 68 (272B rows, 16B-mult)
    __shared__ __align__(16) float Ssn[64][68];   // -lits*k, TRANSPOSED [l][n], pad 68
    __shared__ float ksc[L_];

    int t    = threadIdx.x;
    int lane = t & 31;
    int warp = t >> 5;               // n-group 0..7
    int n0   = blockIdx.x * 64;

    if (t < L_) ksc[t] = sqrtf(LOG2E / var_l[t]);
    __syncthreads();

    // stage -s*k transposed [l][n] (visible after first chunk sync)
    for (int i = t; i < 64 * 64; i += 256) {
        int l = i & 63, nl = i >> 6;
        Ssn[l][nl] = -lits[(long)(n0 + nl) * L_ + l] * ksc[l];
    }

    u64t acc0p[4], acc1p[4];
#pragma unroll
    for (int u = 0; u < 4; u++) { acc0p[u] = pk2(0.f, 0.f); acc1p[u] = pk2(0.f, 0.f); }

    const float2* x2  = (const float2*)g_x1T;
    const float2* aT2 = (const float2*)g_aT;
    const float2* wT2 = (const float2*)g_wT;

    int lc_done = 0;
#pragma unroll 1
    for (int ch = 0; ch < 5; ch++) {
        int d0 = ch * 40;
        __syncthreads();
        for (int i = t; i < 40 * 64; i += 256) {
            int dl = i % 40, nl = i / 40;
            Es[dl][nl] = E[(long)(n0 + nl) * D1_ + d0 + dl];
        }
        __syncthreads();
        // -------- score_l partial: 40 d, FFMA2 over n-pairs --------
#pragma unroll 8
        for (int dl = 0; dl < 40; dl++) {
            float2 xv = x2[(d0 + dl) * 32 + lane];
            u64t x0p = pk2(xv.x, xv.x);
            u64t x1p = pk2(xv.y, xv.y);
            const ulonglong2* ep = (const ulonglong2*)&Es[dl][warp * 8];
            ulonglong2 ea = ep[0], eb = ep[1];
            acc0p[0] = fma2_(x0p, ea.x, acc0p[0]);
            acc0p[1] = fma2_(x0p, ea.y, acc0p[1]);
            acc0p[2] = fma2_(x0p, eb.x, acc0p[2]);
            acc0p[3] = fma2_(x0p, eb.y, acc0p[3]);
            acc1p[0] = fma2_(x1p, ea.x, acc1p[0]);
            acc1p[1] = fma2_(x1p, ea.y, acc1p[1]);
            acc1p[2] = fma2_(x1p, eb.x, acc1p[2]);
            acc1p[3] = fma2_(x1p, eb.y, acc1p[3]);
        }
        // -------- KBLN partial: 3-4 sub-chunks of 4 literals, f32x2 over n-pairs --------
        int nchunks = (ch == 0) ? 4 : 3;
#pragma unroll 1
        for (int r = 0; r < nchunks; r++) {
            int l0 = lc_done * 4;
            u64t aa0[4], aa1[4], ww0[4], ww1[4];
#pragma unroll
            for (int u = 0; u < 4; u++) {
                float2 a2 = aT2[(l0 + u) * 32 + lane];
                float2 w2 = wT2[(l0 + u) * 32 + lane];
                aa0[u] = pk2(a2.x, a2.x); aa1[u] = pk2(a2.y, a2.y);
                ww0[u] = pk2(w2.x, w2.x); ww1[u] = pk2(w2.y, w2.y);
            }
#pragma unroll
            for (int u = 0; u < 4; u++) {
                const ulonglong2* sp = (const ulonglong2*)&Ssn[l0 + u][warp * 8];
                ulonglong2 sA = sp[0], sB = sp[1];
                u64t sv[4] = {sA.x, sA.y, sB.x, sB.y};
#pragma unroll
                for (int np = 0; np < 4; np++) {
                    u64t dd0 = add2_(aa0[u], sv[np]);   // a - s  (Ssn holds -s)
                    u64t mm0 = mul2_(dd0, dd0);
                    float2 m0 = up2(mm0);
                    float p0 = ex2f(-m0.x), p1 = ex2f(-m0.y);
                    acc0p[np] = fma2_(ww0[u], pk2(p0, p1), acc0p[np]);
                    u64t dd1 = add2_(aa1[u], sv[np]);
                    u64t mm1 = mul2_(dd1, dd1);
                    float2 m1 = up2(mm1);
                    float q0 = ex2f(-m1.x), q1 = ex2f(-m1.y);
                    acc1p[np] = fma2_(ww1[u], pk2(q0, q1), acc1p[np]);
                }
            }
            lc_done++;
        }
    }

    // -------- sigmoid + store (2 rows x 8 n per thread) --------
    int b0 = 2 * lane;
    int n  = n0 + warp * 8;
    float2 r0[4], r1[4];
#pragma unroll
    for (int u = 0; u < 4; u++) {
        r0[u] = up2(acc0p[u]); r1[u] = up2(acc1p[u]);
        r0[u].x = rcpf(1.f + ex2f(-LOG2E * r0[u].x));
        r0[u].y = rcpf(1.f + ex2f(-LOG2E * r0[u].y));
        r1[u].x = rcpf(1.f + ex2f(-LOG2E * r1[u].x));
        r1[u].y = rcpf(1.f + ex2f(-LOG2E * r1[u].y));
    }
    float4* o0 = (float4*)&out[(long)b0 * NE_ + n];
    o0[0] = make_float4(r0[0].x, r0[0].y, r0[1].x, r0[1].y);
    o0[1] = make_float4(r0[2].x, r0[2].y, r0[3].x, r0[3].y);
    float4* o1 = (float4*)&out[(long)(b0 + 1) * NE_ + n];
    o1[0] = make_float4(r1[0].x, r1[0].y, r1[1].x, r1[1].y);
    o1[1] = make_float4(r1[2].x, r1[2].y, r1[3].x, r1[3].y);
}

// ---------------- launch ----------------
extern "C" void kernel_launch(void* const* d_in, const int* in_sizes, int n_in,
                              void* d_out, int out_size) {
    const int*   e1_idx = (const int*)  d_in[0];
    const int*   r_idx  = (const int*)  d_in[1];
    const float* E      = (const float*)d_in[2];
    const float* R      = (const float*)d_in[3];
    const float* W      = (const float*)d_in[4];
    const float* lits   = (const float*)d_in[5];
    const float* c      = (const float*)d_in[6];
    const float* var_l  = (const float*)d_in[7];
    const float* nf     = (const float*)d_in[8];
    const float* g0     = (const float*)d_in[9];
    const float* b0     = (const float*)d_in[10];
    const float* g1     = (const float*)d_in[11];
    const float* b1     = (const float*)d_in[12];
    float* out = (float*)d_out;

    k_prep<<<28, 256>>>(e1_idx, r_idx, E, R, lits, c, var_l, nf, g0, b0);
    k_wgemm<<<dim3(7, KSPLIT), 256>>>(W);
    k_bn1r<<<25, 256>>>(g1, b1);
    k_score<<<NE_ / 64, 256>>>(E, lits, var_l, out);
}

// round 10
// speedup vs baseline: 1.6488x; 1.1063x over previous
#include <cuda_runtime.h>
#include <cuda_bf16.h>
#include <cstring>

// Problem constants
#define B_   64
#define NE_  40000
#define NR_  500
#define D1_  200
#define D2_  200
#define L_   64
#define KSPLIT 50          // k2 chunk = 4
#define LOG2E 1.4426950408889634f
#define NKS   14           // K padded to 224 = 14 k16-steps
#define KCHUNK 112         // 7 k-steps per smem chunk
#define EPADK 120          // bf16 row pad for conflict-free B-frag LDS

typedef unsigned int u32t;
typedef unsigned long long u64t;

// ---------------- scratch (device globals; no allocation) ----------------
__device__ __align__(16) float g_x0T[D1_ * B_];          // [i][b]
__device__ __align__(16) float g_rT [D2_ * B_];          // [k][b]
__device__ __align__(16) float g_aT [L_ * B_];           // [l][b]
__device__ __align__(16) float g_wT [L_ * B_];           // [l][b]
__device__ __align__(16) float g_ypart[KSPLIT * D1_ * B_];
__device__ __align__(16) float g_x1T[D1_ * B_];          // [d][b]
__device__ __align__(16) uint4 g_Afrag[2 * NKS * 4 * 32]; // [split][ks][mt][lane]

__device__ __forceinline__ float ex2f(float x) {
    float r; asm("ex2.approx.ftz.f32 %0, %1;" : "=f"(r) : "f"(x)); return r;
}
__device__ __forceinline__ float rcpf(float x) {
    float r; asm("rcp.approx.ftz.f32 %0, %1;" : "=f"(r) : "f"(x)); return r;
}
__device__ __forceinline__ u32t pk2f(float lo, float hi) {
    u64t r; asm("mov.b64 %0, {%1, %2};" : "=l"(r) : "f"(lo), "f"(hi));
    return (u32t)r; // unused helper guard
}
__device__ __forceinline__ u32t pkbf(float x, float y) {
    __nv_bfloat162 h = __floats2bfloat162_rn(x, y);
    u32t r; memcpy(&r, &h, 4); return r;
}
// ---- packed f32x2 helpers (kept for k_wgemm) ----
__device__ __forceinline__ u64t pk2(float lo, float hi) {
    u64t r; asm("mov.b64 %0, {%1, %2};" : "=l"(r) : "f"(lo), "f"(hi)); return r;
}
__device__ __forceinline__ float2 up2(u64t p) {
    float2 v; asm("mov.b64 {%0, %1}, %2;" : "=f"(v.x), "=f"(v.y) : "l"(p)); return v;
}
__device__ __forceinline__ u64t mul2_(u64t a, u64t b) {
    u64t r; asm("mul.rn.f32x2 %0, %1, %2;" : "=l"(r) : "l"(a), "l"(b)); return r;
}
__device__ __forceinline__ u64t fma2_(u64t a, u64t b, u64t c) {
    u64t r; asm("fma.rn.f32x2 %0, %1, %2, %3;" : "=l"(r) : "l"(a), "l"(b), "l"(c)); return r;
}
// bf16 mma m16n8k16 row.col f32 accum
__device__ __forceinline__ void mma16816(float4& c, uint4 a, u32t b0, u32t b1) {
    asm volatile(
        "mma.sync.aligned.m16n8k16.row.col.f32.bf16.bf16.f32 "
        "{%0,%1,%2,%3}, {%4,%5,%6,%7}, {%8,%9}, {%0,%1,%2,%3};"
        : "+f"(c.x), "+f"(c.y), "+f"(c.z), "+f"(c.w)
        : "r"(a.x), "r"(a.y), "r"(a.z), "r"(a.w), "r"(b0), "r"(b1));
}

// ---------------- kernel 1: parallel gather + BN0 + branch prep ----------------
__global__ void k_prep(const int* __restrict__ e1_idx, const int* __restrict__ r_idx,
                       const float* __restrict__ E, const float* __restrict__ R,
                       const float* __restrict__ lits, const float* __restrict__ c,
                       const float* __restrict__ var_l, const float* __restrict__ nf,
                       const float* __restrict__ g0, const float* __restrict__ b0) {
    int blk = blockIdx.x;
    int t = threadIdx.x;
    if (blk < 25) {
        __shared__ int se1[B_];
        if (t < B_) se1[t] = e1_idx[t];
        __syncthreads();
        int j    = blk * 8 + (t >> 5);
        int lane = t & 31;
        float v0 = E[(long)se1[lane] * D1_ + j];
        float v1 = E[(long)se1[lane + 32] * D1_ + j];
        float s = v0 + v1, q = v0 * v0 + v1 * v1;
#pragma unroll
        for (int off = 16; off >= 1; off >>= 1) {
            s += __shfl_xor_sync(0xffffffffu, s, off);
            q += __shfl_xor_sync(0xffffffffu, q, off);
        }
        float mu  = s * (1.f / B_);
        float var = q * (1.f / B_) - mu * mu;
        float sc  = g0[j] * rsqrtf(var + 1e-5f);
        float be  = b0[j];
        g_x0T[j * B_ + lane]      = (v0 - mu) * sc + be;
        g_x0T[j * B_ + 32 + lane] = (v1 - mu) * sc + be;
    } else if (blk < 27) {
        __shared__ int sr[B_];
        if (t < B_) sr[t] = r_idx[t];
        __syncthreads();
        int base = (blk - 25) * (D2_ * B_ / 2);
        for (int idx = t; idx < D2_ * B_ / 2; idx += 256) {
            int k = (base + idx) >> 6, b = (base + idx) & 63;
            g_rT[base + idx] = R[(long)sr[b] * D2_ + k];
        }
    } else {
        __shared__ int se1[B_], sr[B_];
        if (t < B_) { se1[t] = e1_idx[t]; sr[t] = r_idx[t]; }
        __syncthreads();
        for (int idx = t; idx < B_ * L_; idx += 256) {
            int b = idx & 63, l = idx >> 6;
            float ks = sqrtf(LOG2E / var_l[l]);
            g_aT[l * B_ + b] = (lits[(long)se1[b] * L_ + l] - c[l]) * ks;
            g_wT[l * B_ + b] = nf[(long)sr[b] * L_ + l];
        }
    }
}

// ---------------- kernel 2: W GEMM (double-buffered, f32x2 pairs over j) ----------------
__global__ __launch_bounds__(256) void k_wgemm(const float* __restrict__ W) {
    int jt = blockIdx.x;          // 0..6
    int ks = blockIdx.y;          // 0..49
    int t  = threadIdx.x;
    int b  = t & 63;
    int jg = t >> 6;              // 0..3
    int j0 = jt * 32;

    __shared__ __align__(16) float Ws[2][4][20][32];

    u64t rv2[4];
#pragma unroll
    for (int kc = 0; kc < 4; kc++) {
        float rv = g_rT[(ks * 4 + kc) * B_ + b];
        rv2[kc] = pk2(rv, rv);
    }
    u64t accp[4];
#pragma unroll
    for (int u = 0; u < 4; u++) accp[u] = pk2(0.f, 0.f);

    #define STAGE(ch, p) {                                                  \
        int i0_ = (ch) * 20;                                                \
        for (int idx = t; idx < 4 * 20 * 32; idx += 256) {                  \
            int jl = idx & 31;                                              \
            int il = (idx >> 5) % 20;                                       \
            int kc = idx / 640;                                             \
            int j  = j0 + jl;                                               \
            Ws[p][kc][il][jl] = (j < D1_)                                   \
                ? W[((long)(ks * 4 + kc) * D1_ + (i0_ + il)) * D1_ + j] : 0.f; \
        }                                                                   \
    }

    STAGE(0, 0);
#pragma unroll 1
    for (int ch = 0; ch < 10; ch++) {
        __syncthreads();
        if (ch < 9) STAGE(ch + 1, (ch + 1) & 1);
        int p  = ch & 1;
        int i0 = ch * 20;
#pragma unroll 4
        for (int il = 0; il < 20; il++) {
            float xv = g_x0T[(i0 + il) * B_ + b];
            u64t xp = pk2(xv, xv);
#pragma unroll
            for (int kc = 0; kc < 4; kc++) {
                u64t z = mul2_(rv2[kc], xp);
                const ulonglong2* wp = (const ulonglong2*)&Ws[p][kc][il][jg * 8];
                ulonglong2 wa = wp[0], wb = wp[1];
                accp[0] = fma2_(z, wa.x, accp[0]);
                accp[1] = fma2_(z, wa.y, accp[1]);
                accp[2] = fma2_(z, wb.x, accp[2]);
                accp[3] = fma2_(z, wb.y, accp[3]);
            }
        }
    }
    #undef STAGE

    float* yp = &g_ypart[ks * (D1_ * B_)];
    int j = j0 + jg * 8;
#pragma unroll
    for (int u = 0; u < 4; u++) {
        float2 v = up2(accp[u]);
        if (j + 2 * u     < D1_) yp[(j + 2 * u)     * B_ + b] = v.x;
        if (j + 2 * u + 1 < D1_) yp[(j + 2 * u + 1) * B_ + b] = v.y;
    }
}

// ---------------- kernel 3: fused k-split reduce + BN1 -> x1T[d][b] ----------------
__global__ void k_bn1r(const float* __restrict__ g1, const float* __restrict__ b1) {
    int j    = blockIdx.x * 8 + (threadIdx.x >> 5);
    int lane = threadIdx.x & 31;
    float y0 = 0.f, y1 = 0.f;
#pragma unroll 10
    for (int ks = 0; ks < KSPLIT; ks++) {
        y0 += g_ypart[ks * (D1_ * B_) + j * B_ + lane];
        y1 += g_ypart[ks * (D1_ * B_) + j * B_ + 32 + lane];
    }
    float s = y0 + y1, q = y0 * y0 + y1 * y1;
#pragma unroll
    for (int off = 16; off >= 1; off >>= 1) {
        s += __shfl_xor_sync(0xffffffffu, s, off);
        q += __shfl_xor_sync(0xffffffffu, q, off);
    }
    float mu  = s * (1.f / B_);
    float var = q * (1.f / B_) - mu * mu;
    float sc  = g1[j] * rsqrtf(var + 1e-5f);
    float be  = b1[j];
    g_x1T[j * B_ + lane]      = (y0 - mu) * sc + be;
    g_x1T[j * B_ + 32 + lane] = (y1 - mu) * sc + be;
}

// ---------------- kernel 3b: build bf16 hi/lo A-fragments from x1T ----------------
// grid (NKS, 4), 32 threads. Register layout of mma.m16n8k16 A fragment.
__global__ void k_afrag() {
    int ks   = blockIdx.x;       // 0..13
    int mt   = blockIdx.y;       // 0..3
    int lane = threadIdx.x;      // 0..31
    int r0   = mt * 16 + (lane >> 2);
    int c0   = ks * 16 + 2 * (lane & 3);

    float vh[2][4], vl[2][4];
#pragma unroll
    for (int rr = 0; rr < 2; rr++) {
        int r = r0 + rr * 8;
#pragma unroll
        for (int cc = 0; cc < 4; cc++) {
            int c = c0 + (cc & 1) + (cc >> 1) * 8;
            float x = (c < D1_) ? g_x1T[c * B_ + r] : 0.f;
            float h = __bfloat162float(__float2bfloat16_rn(x));
            vh[rr][cc] = h;
            vl[rr][cc] = x - h;
        }
    }
    uint4 H, L;
    H.x = pkbf(vh[0][0], vh[0][1]); H.y = pkbf(vh[1][0], vh[1][1]);
    H.z = pkbf(vh[0][2], vh[0][3]); H.w = pkbf(vh[1][2], vh[1][3]);
    L.x = pkbf(vl[0][0], vl[0][1]); L.y = pkbf(vl[1][0], vl[1][1]);
    L.z = pkbf(vl[0][2], vl[0][3]); L.w = pkbf(vl[1][2], vl[1][3]);
    int base = (ks * 4 + mt) * 32 + lane;
    g_Afrag[base]                 = H;
    g_Afrag[base + NKS * 4 * 32]  = L;
}

// ---------------- kernel 4: tensor score_l + scalar KBLN + sigmoid ----------------
// grid 625 (64 n), block 256 = 8 warps.
// Phase 1 (mma): warp w -> m-tile mt=w%4 (16 b-rows), n-half nh=w/4 (32 n, 4 n8-tiles).
// Phase 2 (KBLN): R4 layout, warp = n-group of 8, lane -> b = 2*lane, 2*lane+1.
__global__ __launch_bounds__(256) void k_score(
    const float* __restrict__ E, const float* __restrict__ lits,
    const float* __restrict__ var_l, float* __restrict__ out) {

    // union buffer: bf16 E-chunk (hi rows 0..63, lo rows 64..127) OR fp32 scores tile
    __shared__ __align__(16) char u_buf[2 * 64 * EPADK * 2];   // 30720 B
    __shared__ __align__(16) float Ssn[64][68];                // -lits*k [l][n]
    __shared__ float ksc[L_];

    __nv_bfloat16* eb = (__nv_bfloat16*)u_buf;                 // eb[row*EPADK + k]
    float (*scores)[76] = (float (*)[76])u_buf;                // 64 x 76 fp32

    int t    = threadIdx.x;
    int lane = t & 31;
    int warp = t >> 5;
    int n0   = blockIdx.x * 64;

    if (t < L_) ksc[t] = sqrtf(LOG2E / var_l[t]);
    __syncthreads();
    // stage Ssn (separate region; consumed in phase 2 after later syncs)
    for (int i = t; i < 64 * 64; i += 256) {
        int l = i & 63, nl = i >> 6;
        Ssn[l][nl] = -lits[(long)(n0 + nl) * L_ + l] * ksc[l];
    }

    // ================= phase 1: score_l via bf16 hi/lo mma =================
    int mt = warp & 3;          // m-tile (16 b-rows)
    int nh = warp >> 2;         // n-half (32 cols)
    float4 acc[4];
#pragma unroll
    for (int u = 0; u < 4; u++) acc[u] = make_float4(0.f, 0.f, 0.f, 0.f);

#pragma unroll 1
    for (int chunk = 0; chunk < 2; chunk++) {
        int kb = chunk * KCHUNK;
        __syncthreads();
        // stage E chunk: 64 rows x 112 k, fp32 -> bf16 hi/lo
        for (int idx = t; idx < 64 * (KCHUNK / 4); idx += 256) {
            int row = idx / (KCHUNK / 4);
            int kq  = (idx % (KCHUNK / 4)) * 4;      // local k, multiple of 4
            int kg  = kb + kq;
            float v0, v1, v2, v3;
            if (kg + 3 < D1_) {
                float4 v = *(const float4*)&E[(long)(n0 + row) * D1_ + kg];
                v0 = v.x; v1 = v.y; v2 = v.z; v3 = v.w;
            } else {
                v0 = (kg     < D1_) ? E[(long)(n0 + row) * D1_ + kg]     : 0.f;
                v1 = (kg + 1 < D1_) ? E[(long)(n0 + row) * D1_ + kg + 1] : 0.f;
                v2 = (kg + 2 < D1_) ? E[(long)(n0 + row) * D1_ + kg + 2] : 0.f;
                v3 = (kg + 3 < D1_) ? E[(long)(n0 + row) * D1_ + kg + 3] : 0.f;
            }
            float h0 = __bfloat162float(__float2bfloat16_rn(v0));
            float h1 = __bfloat162float(__float2bfloat16_rn(v1));
            float h2 = __bfloat162float(__float2bfloat16_rn(v2));
            float h3 = __bfloat162float(__float2bfloat16_rn(v3));
            *(u32t*)&eb[row * EPADK + kq]            = pkbf(h0, h1);
            *(u32t*)&eb[row * EPADK + kq + 2]        = pkbf(h2, h3);
            *(u32t*)&eb[(64 + row) * EPADK + kq]     = pkbf(v0 - h0, v1 - h1);
            *(u32t*)&eb[(64 + row) * EPADK + kq + 2] = pkbf(v2 - h2, v3 - h3);
        }
        __syncthreads();
#pragma unroll 1
        for (int ksl = 0; ksl < 7; ksl++) {
            int ks = chunk * 7 + ksl;
            uint4 AH = g_Afrag[(ks * 4 + mt) * 32 + lane];
            uint4 AL = g_Afrag[(ks * 4 + mt) * 32 + lane + NKS * 4 * 32];
            int kloc = ksl * 16 + 2 * (lane & 3);
#pragma unroll
            for (int tile = 0; tile < 4; tile++) {
                int n = nh * 32 + tile * 8 + (lane >> 2);
                u32t bh0 = *(const u32t*)&eb[n * EPADK + kloc];
                u32t bh1 = *(const u32t*)&eb[n * EPADK + kloc + 8];
                u32t bl0 = *(const u32t*)&eb[(64 + n) * EPADK + kloc];
                u32t bl1 = *(const u32t*)&eb[(64 + n) * EPADK + kloc + 8];
                mma16816(acc[tile], AH, bh0, bh1);
                mma16816(acc[tile], AH, bl0, bl1);
                mma16816(acc[tile], AL, bh0, bh1);
            }
        }
    }
    __syncthreads();   // all B-frag reads done; union becomes scores
    {
        int sr = mt * 16 + (lane >> 2);
        int sc = nh * 32 + 2 * (lane & 3);
#pragma unroll
        for (int tile = 0; tile < 4; tile++) {
            *(float2*)&scores[sr][sc + tile * 8]     = make_float2(acc[tile].x, acc[tile].y);
            *(float2*)&scores[sr + 8][sc + tile * 8] = make_float2(acc[tile].z, acc[tile].w);
        }
    }
    __syncthreads();

    // ================= phase 2: KBLN (scalar, R4 layout) + sigmoid =================
    int b0r = 2 * lane, b1r = b0r + 1;
    float acc0[8], acc1[8];
    {
        float4 sA = *(const float4*)&scores[b0r][warp * 8];
        float4 sB = *(const float4*)&scores[b0r][warp * 8 + 4];
        acc0[0] = sA.x; acc0[1] = sA.y; acc0[2] = sA.z; acc0[3] = sA.w;
        acc0[4] = sB.x; acc0[5] = sB.y; acc0[6] = sB.z; acc0[7] = sB.w;
        float4 tA = *(const float4*)&scores[b1r][warp * 8];
        float4 tB = *(const float4*)&scores[b1r][warp * 8 + 4];
        acc1[0] = tA.x; acc1[1] = tA.y; acc1[2] = tA.z; acc1[3] = tA.w;
        acc1[4] = tB.x; acc1[5] = tB.y; acc1[6] = tB.z; acc1[7] = tB.w;
    }

    const float2* aT2 = (const float2*)g_aT;
    const float2* wT2 = (const float2*)g_wT;
#pragma unroll 1
    for (int lc = 0; lc < 16; lc++) {
        int l0 = lc * 4;
        float2 a2[4], w2[4];
#pragma unroll
        for (int u = 0; u < 4; u++) {
            a2[u] = aT2[(l0 + u) * 32 + lane];
            w2[u] = wT2[(l0 + u) * 32 + lane];
        }
#pragma unroll
        for (int u = 0; u < 4; u++) {
            float4 svA = *(const float4*)&Ssn[l0 + u][warp * 8];
            float4 svB = *(const float4*)&Ssn[l0 + u][warp * 8 + 4];
            float sv[8] = {svA.x, svA.y, svA.z, svA.w, svB.x, svB.y, svB.z, svB.w};
#pragma unroll
            for (int nn = 0; nn < 8; nn++) {
                float d0 = a2[u].x + sv[nn];     // a - s (Ssn holds -s*k)
                float d1 = a2[u].y + sv[nn];
                acc0[nn] += w2[u].x * ex2f(-d0 * d0);
                acc1[nn] += w2[u].y * ex2f(-d1 * d1);
            }
        }
    }

    int n = n0 + warp * 8;
#pragma unroll
    for (int u = 0; u < 8; u++) {
        acc0[u] = rcpf(1.f + ex2f(-LOG2E * acc0[u]));
        acc1[u] = rcpf(1.f + ex2f(-LOG2E * acc1[u]));
    }
    float4* o0 = (float4*)&out[(long)b0r * NE_ + n];
    o0[0] = make_float4(acc0[0], acc0[1], acc0[2], acc0[3]);
    o0[1] = make_float4(acc0[4], acc0[5], acc0[6], acc0[7]);
    float4* o1 = (float4*)&out[(long)b1r * NE_ + n];
    o1[0] = make_float4(acc1[0], acc1[1], acc1[2], acc1[3]);
    o1[1] = make_float4(acc1[4], acc1[5], acc1[6], acc1[7]);
}

// ---------------- launch ----------------
extern "C" void kernel_launch(void* const* d_in, const int* in_sizes, int n_in,
                              void* d_out, int out_size) {
    const int*   e1_idx = (const int*)  d_in[0];
    const int*   r_idx  = (const int*)  d_in[1];
    const float* E      = (const float*)d_in[2];
    const float* R      = (const float*)d_in[3];
    const float* W      = (const float*)d_in[4];
    const float* lits   = (const float*)d_in[5];
    const float* c      = (const float*)d_in[6];
    const float* var_l  = (const float*)d_in[7];
    const float* nf     = (const float*)d_in[8];
    const float* g0     = (const float*)d_in[9];
    const float* b0     = (const float*)d_in[10];
    const float* g1     = (const float*)d_in[11];
    const float* b1     = (const float*)d_in[12];
    float* out = (float*)d_out;

    k_prep<<<28, 256>>>(e1_idx, r_idx, E, R, lits, c, var_l, nf, g0, b0);
    k_wgemm<<<dim3(7, KSPLIT), 256>>>(W);
    k_bn1r<<<25, 256>>>(g1, b1);
    k_afrag<<<dim3(NKS, 4), 32>>>();
    k_score<<<NE_ / 64, 256>>>(E, lits, var_l, out);
}

// round 11
// speedup vs baseline: 1.7593x; 1.0671x over previous
#include <cuda_runtime.h>
#include <cuda_bf16.h>
#include <cstring>

// Problem constants
#define B_   64
#define NE_  40000
#define NR_  500
#define D1_  200
#define D2_  200
#define L_   64
#define KSPLIT 50          // k2 chunk = 4
#define LOG2E 1.4426950408889634f
#define NKS   14           // K padded to 224 = 14 k16-steps (ks 13 stays zero/unused)
#define KCHUNK 112         // 7 k-steps per smem chunk
#define EPADK 120          // bf16 row pad for conflict-free B-frag LDS

typedef unsigned int u32t;
typedef unsigned long long u64t;

// ---------------- scratch (device globals; no allocation) ----------------
__device__ __align__(16) float g_x0T[D1_ * B_];          // [i][b]
__device__ __align__(16) float g_rT [D2_ * B_];          // [k][b]
__device__ __align__(16) float g_aT [L_ * B_];           // [l][b]
__device__ __align__(16) float g_wT [L_ * B_];           // [l][b]
__device__ __align__(16) float g_ypart[KSPLIT * D1_ * B_];
__device__ __align__(16) uint4 g_Afrag[2 * NKS * 4 * 32]; // [split][ks][mt][lane]

__device__ __forceinline__ float ex2f(float x) {
    float r; asm("ex2.approx.ftz.f32 %0, %1;" : "=f"(r) : "f"(x)); return r;
}
__device__ __forceinline__ float rcpf(float x) {
    float r; asm("rcp.approx.ftz.f32 %0, %1;" : "=f"(r) : "f"(x)); return r;
}
__device__ __forceinline__ u32t pkbf(float x, float y) {
    __nv_bfloat162 h = __floats2bfloat162_rn(x, y);
    u32t r; memcpy(&r, &h, 4); return r;
}
// ---- packed f32x2 helpers (k_wgemm) ----
__device__ __forceinline__ u64t pk2(float lo, float hi) {
    u64t r; asm("mov.b64 %0, {%1, %2};" : "=l"(r) : "f"(lo), "f"(hi)); return r;
}
__device__ __forceinline__ float2 up2(u64t p) {
    float2 v; asm("mov.b64 {%0, %1}, %2;" : "=f"(v.x), "=f"(v.y) : "l"(p)); return v;
}
__device__ __forceinline__ u64t mul2_(u64t a, u64t b) {
    u64t r; asm("mul.rn.f32x2 %0, %1, %2;" : "=l"(r) : "l"(a), "l"(b)); return r;
}
__device__ __forceinline__ u64t fma2_(u64t a, u64t b, u64t c) {
    u64t r; asm("fma.rn.f32x2 %0, %1, %2, %3;" : "=l"(r) : "l"(a), "l"(b), "l"(c)); return r;
}
// bf16 mma m16n8k16 row.col f32 accum
__device__ __forceinline__ void mma16816(float4& c, uint4 a, u32t b0, u32t b1) {
    asm volatile(
        "mma.sync.aligned.m16n8k16.row.col.f32.bf16.bf16.f32 "
        "{%0,%1,%2,%3}, {%4,%5,%6,%7}, {%8,%9}, {%0,%1,%2,%3};"
        : "+f"(c.x), "+f"(c.y), "+f"(c.z), "+f"(c.w)
        : "r"(a.x), "r"(a.y), "r"(a.z), "r"(a.w), "r"(b0), "r"(b1));
}
__device__ __forceinline__ void barnamed(int id) {
    asm volatile("bar.sync %0, 128;" :: "r"(id) : "memory");
}

// ---------------- kernel 1: parallel gather + BN0 + branch prep ----------------
__global__ void k_prep(const int* __restrict__ e1_idx, const int* __restrict__ r_idx,
                       const float* __restrict__ E, const float* __restrict__ R,
                       const float* __restrict__ lits, const float* __restrict__ c,
                       const float* __restrict__ var_l, const float* __restrict__ nf,
                       const float* __restrict__ g0, const float* __restrict__ b0) {
    int blk = blockIdx.x;
    int t = threadIdx.x;
    if (blk < 25) {
        __shared__ int se1[B_];
        if (t < B_) se1[t] = e1_idx[t];
        __syncthreads();
        int j    = blk * 8 + (t >> 5);
        int lane = t & 31;
        float v0 = E[(long)se1[lane] * D1_ + j];
        float v1 = E[(long)se1[lane + 32] * D1_ + j];
        float s = v0 + v1, q = v0 * v0 + v1 * v1;
#pragma unroll
        for (int off = 16; off >= 1; off >>= 1) {
            s += __shfl_xor_sync(0xffffffffu, s, off);
            q += __shfl_xor_sync(0xffffffffu, q, off);
        }
        float mu  = s * (1.f / B_);
        float var = q * (1.f / B_) - mu * mu;
        float sc  = g0[j] * rsqrtf(var + 1e-5f);
        float be  = b0[j];
        g_x0T[j * B_ + lane]      = (v0 - mu) * sc + be;
        g_x0T[j * B_ + 32 + lane] = (v1 - mu) * sc + be;
    } else if (blk < 27) {
        __shared__ int sr[B_];
        if (t < B_) sr[t] = r_idx[t];
        __syncthreads();
        int base = (blk - 25) * (D2_ * B_ / 2);
        for (int idx = t; idx < D2_ * B_ / 2; idx += 256) {
            int k = (base + idx) >> 6, b = (base + idx) & 63;
            g_rT[base + idx] = R[(long)sr[b] * D2_ + k];
        }
    } else {
        __shared__ int se1[B_], sr[B_];
        if (t < B_) { se1[t] = e1_idx[t]; sr[t] = r_idx[t]; }
        __syncthreads();
        for (int idx = t; idx < B_ * L_; idx += 256) {
            int b = idx & 63, l = idx >> 6;
            float ks = sqrtf(LOG2E / var_l[l]);
            g_aT[l * B_ + b] = (lits[(long)se1[b] * L_ + l] - c[l]) * ks;
            g_wT[l * B_ + b] = nf[(long)sr[b] * L_ + l];
        }
    }
}

// ---------------- kernel 2: W GEMM (double-buffered, f32x2 pairs over j) ----------------
__global__ __launch_bounds__(256) void k_wgemm(const float* __restrict__ W) {
    int jt = blockIdx.x;          // 0..6
    int ks = blockIdx.y;          // 0..49
    int t  = threadIdx.x;
    int b  = t & 63;
    int jg = t >> 6;              // 0..3
    int j0 = jt * 32;

    __shared__ __align__(16) float Ws[2][4][20][32];

    u64t rv2[4];
#pragma unroll
    for (int kc = 0; kc < 4; kc++) {
        float rv = g_rT[(ks * 4 + kc) * B_ + b];
        rv2[kc] = pk2(rv, rv);
    }
    u64t accp[4];
#pragma unroll
    for (int u = 0; u < 4; u++) accp[u] = pk2(0.f, 0.f);

    #define STAGE(ch, p) {                                                  \
        int i0_ = (ch) * 20;                                                \
        for (int idx = t; idx < 4 * 20 * 32; idx += 256) {                  \
            int jl = idx & 31;                                              \
            int il = (idx >> 5) % 20;                                       \
            int kc = idx / 640;                                             \
            int j  = j0 + jl;                                               \
            Ws[p][kc][il][jl] = (j < D1_)                                   \
                ? W[((long)(ks * 4 + kc) * D1_ + (i0_ + il)) * D1_ + j] : 0.f; \
        }                                                                   \
    }

    STAGE(0, 0);
#pragma unroll 1
    for (int ch = 0; ch < 10; ch++) {
        __syncthreads();
        if (ch < 9) STAGE(ch + 1, (ch + 1) & 1);
        int p  = ch & 1;
        int i0 = ch * 20;
#pragma unroll 4
        for (int il = 0; il < 20; il++) {
            float xv = g_x0T[(i0 + il) * B_ + b];
            u64t xp = pk2(xv, xv);
#pragma unroll
            for (int kc = 0; kc < 4; kc++) {
                u64t z = mul2_(rv2[kc], xp);
                const ulonglong2* wp = (const ulonglong2*)&Ws[p][kc][il][jg * 8];
                ulonglong2 wa = wp[0], wb = wp[1];
                accp[0] = fma2_(z, wa.x, accp[0]);
                accp[1] = fma2_(z, wa.y, accp[1]);
                accp[2] = fma2_(z, wb.x, accp[2]);
                accp[3] = fma2_(z, wb.y, accp[3]);
            }
        }
    }
    #undef STAGE

    float* yp = &g_ypart[ks * (D1_ * B_)];
    int j = j0 + jg * 8;
#pragma unroll
    for (int u = 0; u < 4; u++) {
        float2 v = up2(accp[u]);
        if (j + 2 * u     < D1_) yp[(j + 2 * u)     * B_ + b] = v.x;
        if (j + 2 * u + 1 < D1_) yp[(j + 2 * u + 1) * B_ + b] = v.y;
    }
}

// ---------------- kernel 3: reduce + BN1 + A-fragment build (fused) ----------------
// grid 13, block 512 = 16 warps. Warp w handles j = blk*16 + w (reduce+BN into smem).
// Then warps 0..3 emit bf16 hi/lo mma A-fragments for ks = blk, mt = warp.
__global__ __launch_bounds__(512) void k_bn1f(const float* __restrict__ g1,
                                              const float* __restrict__ b1) {
    __shared__ float x1s[16][64];   // [j_local][b]
    int t    = threadIdx.x;
    int wid  = t >> 5;
    int lane = t & 31;
    int blk  = blockIdx.x;
    int j    = blk * 16 + wid;

    if (j < D1_) {
        float y0 = 0.f, y1 = 0.f;
#pragma unroll 10
        for (int ks = 0; ks < KSPLIT; ks++) {
            y0 += g_ypart[ks * (D1_ * B_) + j * B_ + lane];
            y1 += g_ypart[ks * (D1_ * B_) + j * B_ + 32 + lane];
        }
        float s = y0 + y1, q = y0 * y0 + y1 * y1;
#pragma unroll
        for (int off = 16; off >= 1; off >>= 1) {
            s += __shfl_xor_sync(0xffffffffu, s, off);
            q += __shfl_xor_sync(0xffffffffu, q, off);
        }
        float mu  = s * (1.f / B_);
        float var = q * (1.f / B_) - mu * mu;
        float sc  = g1[j] * rsqrtf(var + 1e-5f);
        float be  = b1[j];
        x1s[wid][lane]      = (y0 - mu) * sc + be;
        x1s[wid][lane + 32] = (y1 - mu) * sc + be;
    } else {
        x1s[wid][lane] = 0.f;
        x1s[wid][lane + 32] = 0.f;
    }
    __syncthreads();

    if (wid < 4) {
        int mt = wid;
        int r0 = mt * 16 + (lane >> 2);
        int c0 = 2 * (lane & 3);
        float vh[2][4], vl[2][4];
#pragma unroll
        for (int rr = 0; rr < 2; rr++) {
            int r = r0 + rr * 8;
#pragma unroll
            for (int cc = 0; cc < 4; cc++) {
                int cl = c0 + (cc & 1) + (cc >> 1) * 8;
                float x = x1s[cl][r];
                float h = __bfloat162float(__float2bfloat16_rn(x));
                vh[rr][cc] = h;
                vl[rr][cc] = x - h;
            }
        }
        uint4 H, L;
        H.x = pkbf(vh[0][0], vh[0][1]); H.y = pkbf(vh[1][0], vh[1][1]);
        H.z = pkbf(vh[0][2], vh[0][3]); H.w = pkbf(vh[1][2], vh[1][3]);
        L.x = pkbf(vl[0][0], vl[0][1]); L.y = pkbf(vl[1][0], vl[1][1]);
        L.z = pkbf(vl[0][2], vl[0][3]); L.w = pkbf(vl[1][2], vl[1][3]);
        int base = (blk * 4 + mt) * 32 + lane;
        g_Afrag[base]                = H;
        g_Afrag[base + NKS * 4 * 32] = L;
    }
}

// ---------------- kernel 4: warp-specialized score (tensor mma || MUFU KBLN) ----------------
// grid 625 (64 n), block 256 = 8 warps:
//   warps 0-3 (SMSP 0-3): score_l via bf16 hi/lo mma (mt = warp, all 64 n)
//   warps 4-7 (SMSP 0-3): KBLN (warp owns 16 n x 64 b, acc in regs), then combine+sigmoid+store
__global__ __launch_bounds__(256) void k_score(
    const float* __restrict__ E, const float* __restrict__ lits,
    const float* __restrict__ var_l, float* __restrict__ out) {

    __shared__ __align__(16) char u_buf[2 * 64 * EPADK * 2];   // E bf16 hi/lo OR fp32 scores
    __shared__ __align__(16) float Ssn[64][68];                // -lits*k [l][n]

    __nv_bfloat16* eb = (__nv_bfloat16*)u_buf;
    float (*scores)[76] = (float (*)[76])u_buf;

    int t    = threadIdx.x;
    int lane = t & 31;
    int warp = t >> 5;
    int n0   = blockIdx.x * 64;

    if (warp < 4) {
        // ================= mma group: threads 0..127 =================
        int mt = warp;
        float4 acc[8];
#pragma unroll
        for (int u = 0; u < 8; u++) acc[u] = make_float4(0.f, 0.f, 0.f, 0.f);

#pragma unroll 1
        for (int chunk = 0; chunk < 2; chunk++) {
            int kb = chunk * KCHUNK;
            // stage E chunk: 64 rows x 112 k, fp32 -> bf16 hi/lo (128 threads)
            for (int idx = t; idx < 64 * (KCHUNK / 4); idx += 128) {
                int row = idx / (KCHUNK / 4);
                int kq  = (idx % (KCHUNK / 4)) * 4;
                int kg  = kb + kq;
                float v0, v1, v2, v3;
                if (kg + 3 < D1_) {
                    float4 v = *(const float4*)&E[(long)(n0 + row) * D1_ + kg];
                    v0 = v.x; v1 = v.y; v2 = v.z; v3 = v.w;
                } else {
                    v0 = (kg     < D1_) ? E[(long)(n0 + row) * D1_ + kg]     : 0.f;
                    v1 = (kg + 1 < D1_) ? E[(long)(n0 + row) * D1_ + kg + 1] : 0.f;
                    v2 = (kg + 2 < D1_) ? E[(long)(n0 + row) * D1_ + kg + 2] : 0.f;
                    v3 = (kg + 3 < D1_) ? E[(long)(n0 + row) * D1_ + kg + 3] : 0.f;
                }
                float h0 = __bfloat162float(__float2bfloat16_rn(v0));
                float h1 = __bfloat162float(__float2bfloat16_rn(v1));
                float h2 = __bfloat162float(__float2bfloat16_rn(v2));
                float h3 = __bfloat162float(__float2bfloat16_rn(v3));
                *(u32t*)&eb[row * EPADK + kq]            = pkbf(h0, h1);
                *(u32t*)&eb[row * EPADK + kq + 2]        = pkbf(h2, h3);
                *(u32t*)&eb[(64 + row) * EPADK + kq]     = pkbf(v0 - h0, v1 - h1);
                *(u32t*)&eb[(64 + row) * EPADK + kq + 2] = pkbf(v2 - h2, v3 - h3);
            }
            barnamed(1);
            int kslim = chunk ? 6 : 7;   // ks 13 (k>=208) is all-zero: skip
#pragma unroll 1
            for (int ksl = 0; ksl < kslim; ksl++) {
                int ks = chunk * 7 + ksl;
                uint4 AH = g_Afrag[(ks * 4 + mt) * 32 + lane];
                uint4 AL = g_Afrag[(ks * 4 + mt) * 32 + lane + NKS * 4 * 32];
                int kloc = ksl * 16 + 2 * (lane & 3);
#pragma unroll
                for (int tile = 0; tile < 8; tile++) {
                    int n = tile * 8 + (lane >> 2);
                    u32t bh0 = *(const u32t*)&eb[n * EPADK + kloc];
                    u32t bh1 = *(const u32t*)&eb[n * EPADK + kloc + 8];
                    u32t bl0 = *(const u32t*)&eb[(64 + n) * EPADK + kloc];
                    u32t bl1 = *(const u32t*)&eb[(64 + n) * EPADK + kloc + 8];
                    mma16816(acc[tile], AH, bh0, bh1);
                    mma16816(acc[tile], AH, bl0, bl1);
                    mma16816(acc[tile], AL, bh0, bh1);
                }
            }
            barnamed(1);   // all reads of this chunk done before restage/score write
        }
        // write score_l tile into union buffer
        {
            int sr = mt * 16 + (lane >> 2);
            int sc = 2 * (lane & 3);
#pragma unroll
            for (int tile = 0; tile < 8; tile++) {
                *(float2*)&scores[sr][sc + tile * 8]     = make_float2(acc[tile].x, acc[tile].y);
                *(float2*)&scores[sr + 8][sc + tile * 8] = make_float2(acc[tile].z, acc[tile].w);
            }
        }
        __syncthreads();   // join
    } else {
        // ================= KBLN group: threads 128..255 =================
        int tl = t - 128;
        // stage Ssn = -lits*k, transposed [l][n]
        for (int i = tl; i < 64 * 64; i += 128) {
            int l = i & 63, nl = i >> 6;
            float ks = sqrtf(LOG2E / var_l[l]);
            Ssn[l][nl] = -lits[(long)(n0 + nl) * L_ + l] * ks;
        }
        barnamed(2);

        int nbase = (warp - 4) * 16;
        float acc0[16], acc1[16];
#pragma unroll
        for (int u = 0; u < 16; u++) { acc0[u] = 0.f; acc1[u] = 0.f; }

        const float2* aT2 = (const float2*)g_aT;
        const float2* wT2 = (const float2*)g_wT;
#pragma unroll 1
        for (int lc = 0; lc < 16; lc++) {
            int l0 = lc * 4;
            float2 a2[4], w2[4];
#pragma unroll
            for (int u = 0; u < 4; u++) {
                a2[u] = aT2[(l0 + u) * 32 + lane];
                w2[u] = wT2[(l0 + u) * 32 + lane];
            }
#pragma unroll
            for (int u = 0; u < 4; u++) {
                float4 svA = *(const float4*)&Ssn[l0 + u][nbase];
                float4 svB = *(const float4*)&Ssn[l0 + u][nbase + 4];
                float4 svC = *(const float4*)&Ssn[l0 + u][nbase + 8];
                float4 svD = *(const float4*)&Ssn[l0 + u][nbase + 12];
                float sv[16] = {svA.x, svA.y, svA.z, svA.w, svB.x, svB.y, svB.z, svB.w,
                                svC.x, svC.y, svC.z, svC.w, svD.x, svD.y, svD.z, svD.w};
#pragma unroll
                for (int nn = 0; nn < 16; nn++) {
                    float d0 = a2[u].x + sv[nn];     // a - s  (Ssn holds -s*k)
                    float d1 = a2[u].y + sv[nn];
                    acc0[nn] += w2[u].x * ex2f(-d0 * d0);
                    acc1[nn] += w2[u].y * ex2f(-d1 * d1);
                }
            }
        }
        __syncthreads();   // join: scores_l now in smem

        // combine + sigmoid + store: thread owns b = 2*lane, 2*lane+1; n = nbase..+15
        int b0r = 2 * lane, b1r = b0r + 1;
#pragma unroll
        for (int g = 0; g < 4; g++) {
            float4 s0 = *(const float4*)&scores[b0r][nbase + g * 4];
            float4 s1 = *(const float4*)&scores[b1r][nbase + g * 4];
            float o0x = rcpf(1.f + ex2f(-LOG2E * (s0.x + acc0[g * 4 + 0])));
            float o0y = rcpf(1.f + ex2f(-LOG2E * (s0.y + acc0[g * 4 + 1])));
            float o0z = rcpf(1.f + ex2f(-LOG2E * (s0.z + acc0[g * 4 + 2])));
            float o0w = rcpf(1.f + ex2f(-LOG2E * (s0.w + acc0[g * 4 + 3])));
            float o1x = rcpf(1.f + ex2f(-LOG2E * (s1.x + acc1[g * 4 + 0])));
            float o1y = rcpf(1.f + ex2f(-LOG2E * (s1.y + acc1[g * 4 + 1])));
            float o1z = rcpf(1.f + ex2f(-LOG2E * (s1.z + acc1[g * 4 + 2])));
            float o1w = rcpf(1.f + ex2f(-LOG2E * (s1.w + acc1[g * 4 + 3])));
            int n = n0 + nbase + g * 4;
            *(float4*)&out[(long)b0r * NE_ + n] = make_float4(o0x, o0y, o0z, o0w);
            *(float4*)&out[(long)b1r * NE_ + n] = make_float4(o1x, o1y, o1z, o1w);
        }
    }
}

// ---------------- launch ----------------
extern "C" void kernel_launch(void* const* d_in, const int* in_sizes, int n_in,
                              void* d_out, int out_size) {
    const int*   e1_idx = (const int*)  d_in[0];
    const int*   r_idx  = (const int*)  d_in[1];
    const float* E      = (const float*)d_in[2];
    const float* R      = (const float*)d_in[3];
    const float* W      = (const float*)d_in[4];
    const float* lits   = (const float*)d_in[5];
    const float* c      = (const float*)d_in[6];
    const float* var_l  = (const float*)d_in[7];
    const float* nf     = (const float*)d_in[8];
    const float* g0     = (const float*)d_in[9];
    const float* b0     = (const float*)d_in[10];
    const float* g1     = (const float*)d_in[11];
    const float* b1     = (const float*)d_in[12];
    float* out = (float*)d_out;

    k_prep<<<28, 256>>>(e1_idx, r_idx, E, R, lits, c, var_l, nf, g0, b0);
    k_wgemm<<<dim3(7, KSPLIT), 256>>>(W);
    k_bn1f<<<13, 512>>>(g1, b1);
    k_score<<<NE_ / 64, 256>>>(E, lits, var_l, out);
}